// round 10
// baseline (speedup 1.0000x reference)
#include <cuda_runtime.h>
#include <math.h>

#define BATCH   128
#define IN_DIM  784
#define HIDDEN  100
#define MODES   10
#define NSTATES 2002
#define NCLS    10
#define SPLIT   2            // level-5 halves per batch

// level sizes: k=1:10  k=2:55  k=3:220  k=4:715  k=5:2002  (total 3002)
#define L2OFF 10
#define L3OFF 65
#define L4OFF 285
#define L5OFF 1000
#define NTOT  3002

// ---------------- scratch (__device__ globals; no allocation allowed) ------
__device__ float g_h[BATCH * HIDDEN];              // sigmoid activations
__device__ float g_part[BATCH * SPLIT * NCLS];     // partial W2 sums
__device__ float g_invfact[NSTATES];               // 1/prod(fact)
__device__ int   g_links[NTOT * 5];                // packed: rank | row<<16 | mult<<24
__device__ int   g_cnt[BATCH];                     // finisher counters (zero-init)

// binomial C(n,k), n=0..13, k=0..4
__device__ const short g_binom[14][5] = {
    {1, 0, 0, 0, 0},  {1, 1, 0, 0, 0},   {1, 2, 1, 0, 0},    {1, 3, 3, 1, 0},
    {1, 4, 6, 4, 1},  {1, 5,10,10, 5},   {1, 6,15,20,15},    {1, 7,21,35,35},
    {1, 8,28,56,70},  {1, 9,36,84,126},  {1,10,45,120,210},  {1,11,55,165,330},
    {1,12,66,220,495},{1,13,78,286,715}
};

__device__ __forceinline__ float2 cmul(float2 a, float2 b) {
    return make_float2(fmaf(a.x, b.x, -(a.y * b.y)),
                       fmaf(a.x, b.y,  a.y * b.x));
}

// ---------------- kernel 1: MLP (blocks 0..399) + link builder (400..411) --
__global__ void __launch_bounds__(256) k_mlp(const float* __restrict__ x,
                                             const float* __restrict__ W1,
                                             const float* __restrict__ b1) {
    int wid  = threadIdx.x >> 5;
    int lane = threadIdx.x & 31;

    if (blockIdx.x >= 400) {
        // ---- build multiset-lattice link tables ----
        int t = (blockIdx.x - 400) * 256 + threadIdx.x;
        if (t >= NTOT) return;
        int k, s;
        if      (t < L2OFF) { k = 1; s = t; }
        else if (t < L3OFF) { k = 2; s = t - L2OFF; }
        else if (t < L4OFF) { k = 3; s = t - L3OFF; }
        else if (t < L5OFF) { k = 4; s = t - L4OFF; }
        else                { k = 5; s = t - L5OFF; }

        // unrank cwr(10, k), rank s -> sorted tuple m[0..k-1]
        int m[5];
        {
            int r = s, prev = 0;
            for (int i = 0; i < k; i++) {
                int vv = prev;
                for (;;) {
                    int c = g_binom[8 + k - vv][k - 1 - i];
                    if (r < c) break;
                    r -= c; vv++;
                }
                m[i] = vv - i; prev = vv + 1;
            }
        }

        int links[5];
        int nl = 0;
        if (k >= 2) {
            for (int d = 0; d < k; d++) {
                if (d > 0 && m[d] == m[d - 1]) continue;   // first occurrence only
                int mult = 1;
                for (int e = d + 1; e < k && m[e] == m[d]; e++) mult++;
                int ch[4];
                int pp = 0;
                for (int e = 0; e < k; e++) if (e != d) ch[pp++] = m[e];
                // rank child tuple at level K = k-1
                int K = k - 1;
                int rank = 0, prev = 0;
                for (int i = 0; i < K; i++) {
                    int ni = ch[i] + i;
                    for (int v = prev; v < ni; v++)
                        rank += g_binom[8 + K - v][K - 1 - i];
                    prev = ni + 1;
                }
                links[nl++] = (rank & 0xFFFF) | (m[d] << 16) | (mult << 24);
            }
        }
        for (int j = nl; j < 5; j++) links[j] = 0;   // mult=0 pad: contributes 0
        for (int j = 0; j < 5; j++) g_links[t * 5 + j] = links[j];

        if (k == 5) {
            int fact = 1, run = 1;
            for (int i = 1; i < 5; i++) {
                if (m[i] == m[i - 1]) { run++; fact *= run; }
                else run = 1;
            }
            g_invfact[s] = 1.0f / (float)fact;
        }
        return;
    }

    // ---- MLP: 2b x 4h warp tiles, K-split x2 (unchanged from R7) ----
    int pid = wid >> 1;
    int kh  = wid & 1;
    int g   = blockIdx.x * 4 + pid;
    int b0  = (g & 63) * 2;
    int h0  = (g >> 6) * 4;

    __shared__ float part[4][8];

    const float4* xr0 = (const float4*)(x  + (b0 + 0) * IN_DIM) + kh * 98;
    const float4* xr1 = (const float4*)(x  + (b0 + 1) * IN_DIM) + kh * 98;
    const float4* wr0 = (const float4*)(W1 + (h0 + 0) * IN_DIM) + kh * 98;
    const float4* wr1 = (const float4*)(W1 + (h0 + 1) * IN_DIM) + kh * 98;
    const float4* wr2 = (const float4*)(W1 + (h0 + 2) * IN_DIM) + kh * 98;
    const float4* wr3 = (const float4*)(W1 + (h0 + 3) * IN_DIM) + kh * 98;

    float v[8];
#pragma unroll
    for (int i = 0; i < 8; i++) v[i] = 0.f;

    const float4 z4 = make_float4(0.f, 0.f, 0.f, 0.f);
#pragma unroll
    for (int t = 0; t < 4; t++) {
        int idx = lane + 32 * t;
        bool ok = (idx < 98);
        float4 x0 = ok ? xr0[idx] : z4;
        float4 x1 = ok ? xr1[idx] : z4;
        float4 w0 = ok ? wr0[idx] : z4;
        float4 w1 = ok ? wr1[idx] : z4;
        float4 w2 = ok ? wr2[idx] : z4;
        float4 w3 = ok ? wr3[idx] : z4;
#pragma unroll
        for (int j = 0; j < 4; j++) {
            float4 wv = (j == 0) ? w0 : (j == 1) ? w1 : (j == 2) ? w2 : w3;
            float a0 = v[j], a1 = v[4 + j];
            a0 = fmaf(x0.x, wv.x, a0); a0 = fmaf(x0.y, wv.y, a0);
            a0 = fmaf(x0.z, wv.z, a0); a0 = fmaf(x0.w, wv.w, a0);
            a1 = fmaf(x1.x, wv.x, a1); a1 = fmaf(x1.y, wv.y, a1);
            a1 = fmaf(x1.z, wv.z, a1); a1 = fmaf(x1.w, wv.w, a1);
            v[j] = a0; v[4 + j] = a1;
        }
    }
#pragma unroll
    for (int i = 0; i < 4; i++) {
        float send = (lane & 16) ? v[i] : v[i + 4];
        float recv = __shfl_xor_sync(0xffffffffu, send, 16);
        v[i] = ((lane & 16) ? v[i + 4] : v[i]) + recv;
    }
#pragma unroll
    for (int i = 0; i < 2; i++) {
        float send = (lane & 8) ? v[i] : v[i + 2];
        float recv = __shfl_xor_sync(0xffffffffu, send, 8);
        v[i] = ((lane & 8) ? v[i + 2] : v[i]) + recv;
    }
    {
        float send = (lane & 4) ? v[0] : v[1];
        float recv = __shfl_xor_sync(0xffffffffu, send, 4);
        v[0] = ((lane & 4) ? v[1] : v[0]) + recv;
    }
    v[0] += __shfl_xor_sync(0xffffffffu, v[0], 2);
    v[0] += __shfl_xor_sync(0xffffffffu, v[0], 1);

    int k = (((lane >> 4) & 1) << 2) | (((lane >> 3) & 1) << 1) | ((lane >> 2) & 1);
    int bi = (k >> 2) & 1, j = k & 3;

    if (kh == 1 && (lane & 3) == 0) part[pid][k] = v[0];
    __syncthreads();
    if (kh == 0 && (lane & 3) == 0) {
        float z = v[0] + part[pid][k] + b1[h0 + j];
        g_h[(b0 + bi) * HIDDEN + h0 + j] = 1.0f / (1.0f + expf(-z));
    }
}

// ---------------- kernel 2: phase+A, lattice permanents, W2 + finisher ----
__global__ void __launch_bounds__(256) k_perm(const float* __restrict__ wlre,
                                              const float* __restrict__ wlim,
                                              const float* __restrict__ wrre,
                                              const float* __restrict__ wrim,
                                              const float* __restrict__ W2,
                                              const float* __restrict__ b2,
                                              float* __restrict__ out) {
    int b = blockIdx.y, chunk = blockIdx.x, tid = threadIdx.x;
    __shared__ float2 ph[MODES];
    __shared__ float2 Ash[50];
    __shared__ float2 p1[10];
    __shared__ float2 p2[55];
    __shared__ float2 p3[220];
    __shared__ float2 p4[715];
    __shared__ float  red[NCLS][8];
    __shared__ int    amLast;

    if (tid < MODES) {
        float th = 0.f;
#pragma unroll
        for (int j = 0; j < 10; j++) th += g_h[b * HIDDEN + j * 10 + tid];
        float sn, cn;
        sincosf(th, &sn, &cn);
        ph[tid] = make_float2(cn, sn);
    }
    __syncthreads();

    if (tid < 50) {
        int p = tid / 5, j = tid % 5, c = 2 * j;   // IN_COLS = {0,2,4,6,8}
        float2 acc = make_float2(0.f, 0.f);
#pragma unroll
        for (int q = 0; q < MODES; q++) {
            float2 wr = make_float2(wrre[p * 10 + q], wrim[p * 10 + q]);
            float2 wl = make_float2(wlre[q * 10 + c], wlim[q * 10 + c]);
            float2 t  = cmul(cmul(wr, ph[q]), wl);
            acc.x += t.x; acc.y += t.y;
        }
        Ash[tid] = acc;
    }
    __syncthreads();

    // ---- level 1: perm of 1x1 = A[r][0] ----
    if (tid < 10) p1[tid] = Ash[tid * 5 + 0];
    __syncthreads();

    // ---- level 2: 55 states, column 1 ----
    if (tid < 55) {
        const int* L = &g_links[(L2OFF + tid) * 5];
        float2 acc = make_float2(0.f, 0.f);
#pragma unroll
        for (int j = 0; j < 5; j++) {
            int e = L[j];
            int c = e & 0xFFFF, r = (e >> 16) & 0xFF;
            float mu = (float)(e >> 24);
            float2 t = cmul(Ash[r * 5 + 1], p1[c]);
            acc.x = fmaf(mu, t.x, acc.x);
            acc.y = fmaf(mu, t.y, acc.y);
        }
        p2[tid] = acc;
    }
    __syncthreads();

    // ---- level 3: 220 states, column 2 ----
    if (tid < 220) {
        const int* L = &g_links[(L3OFF + tid) * 5];
        float2 acc = make_float2(0.f, 0.f);
#pragma unroll
        for (int j = 0; j < 5; j++) {
            int e = L[j];
            int c = e & 0xFFFF, r = (e >> 16) & 0xFF;
            float mu = (float)(e >> 24);
            float2 t = cmul(Ash[r * 5 + 2], p2[c]);
            acc.x = fmaf(mu, t.x, acc.x);
            acc.y = fmaf(mu, t.y, acc.y);
        }
        p3[tid] = acc;
    }
    __syncthreads();

    // ---- level 4: 715 states, column 3 ----
    for (int s = tid; s < 715; s += 256) {
        const int* L = &g_links[(L4OFF + s) * 5];
        float2 acc = make_float2(0.f, 0.f);
#pragma unroll
        for (int j = 0; j < 5; j++) {
            int e = L[j];
            int c = e & 0xFFFF, r = (e >> 16) & 0xFF;
            float mu = (float)(e >> 24);
            float2 t = cmul(Ash[r * 5 + 3], p3[c]);
            acc.x = fmaf(mu, t.x, acc.x);
            acc.y = fmaf(mu, t.y, acc.y);
        }
        p4[s] = acc;
    }
    __syncthreads();

    // ---- level 5 (this chunk's half) + fused W2 accumulation ----
    float acc10[NCLS];
#pragma unroll
    for (int c = 0; c < NCLS; c++) acc10[c] = 0.f;

    int base = chunk * 1001;                       // 2002 = 2 x 1001
#pragma unroll
    for (int it = 0; it < 4; it++) {
        int local = tid + it * 256;
        if (local < 1001) {
            int sg = base + local;
            const int* L = &g_links[(L5OFF + sg) * 5];
            float2 a = make_float2(0.f, 0.f);
#pragma unroll
            for (int j = 0; j < 5; j++) {
                int e = L[j];
                int c = e & 0xFFFF, r = (e >> 16) & 0xFF;
                float mu = (float)(e >> 24);
                float2 t = cmul(Ash[r * 5 + 4], p4[c]);
                a.x = fmaf(mu, t.x, a.x);
                a.y = fmaf(mu, t.y, a.y);
            }
            float p = (a.x * a.x + a.y * a.y) * g_invfact[sg];
#pragma unroll
            for (int c = 0; c < NCLS; c++)
                acc10[c] = fmaf(p, W2[c * NSTATES + sg], acc10[c]);
        }
    }

    // ---- block reduction of 10 class accumulators ----
    int w = tid >> 5, lane = tid & 31;
#pragma unroll
    for (int c = 0; c < NCLS; c++) {
        float v = acc10[c];
#pragma unroll
        for (int o = 16; o; o >>= 1) v += __shfl_xor_sync(0xffffffffu, v, o);
        if (lane == 0) red[c][w] = v;
    }
    __syncthreads();
    if (tid < NCLS) {
        float v = 0.f;
#pragma unroll
        for (int ww = 0; ww < 8; ww++) v += red[tid][ww];
        g_part[(b * SPLIT + chunk) * NCLS + tid] = v;
    }

    // ---- deterministic last-block finisher for this batch ----
    __syncthreads();
    if (tid == 0) {
        __threadfence();
        int old = atomicAdd(&g_cnt[b], 1);
        amLast = (old == SPLIT - 1) ? 1 : 0;
    }
    __syncthreads();
    if (amLast) {
        __threadfence();
        if (tid < NCLS) {
            float v = b2[tid];
#pragma unroll
            for (int k = 0; k < SPLIT; k++)
                v += g_part[(b * SPLIT + k) * NCLS + tid];
            out[b * NCLS + tid] = v;
        }
        if (tid == 0) g_cnt[b] = 0;    // reset for next graph replay
    }
}

// ---------------- launch ---------------------------------------------------
extern "C" void kernel_launch(void* const* d_in, const int* in_sizes, int n_in,
                              void* d_out, int out_size) {
    const float* x    = (const float*)d_in[0];
    const float* W1   = (const float*)d_in[1];
    const float* b1   = (const float*)d_in[2];
    const float* wlre = (const float*)d_in[3];
    const float* wlim = (const float*)d_in[4];
    const float* wrre = (const float*)d_in[5];
    const float* wrim = (const float*)d_in[6];
    const float* W2   = (const float*)d_in[7];
    const float* b2   = (const float*)d_in[8];
    float* out = (float*)d_out;

    k_mlp<<<412, 256>>>(x, W1, b1);
    dim3 gp(SPLIT, BATCH);
    k_perm<<<gp, 256>>>(wlre, wlim, wrre, wrim, W2, b2, out);
}